// round 2
// baseline (speedup 1.0000x reference)
#include <cuda_runtime.h>

#define B_    16
#define D_    64
#define N_    256      // H*W
#define E_    64
#define HID_  128
#define OUT_  64
#define IN_   192      // 2*D + E
#define R_PAIRS 32640  // N*(N-1)/2
#define TI    8        // i-tile size in pair kernel
#define NT    32       // n per uv block
#define WH    8        // warps (h values) per uv block

// Scratch: U,V h-major [b][h][n]
__device__ float g_U[B_ * HID_ * N_];
__device__ float g_V[B_ * HID_ * N_];
__device__ float g_C[B_ * HID_];
__device__ float g_Sabs[B_ * HID_];   // sum of |u_i + v_j + c| over i<j

// ---------------------------------------------------------------------------
// Kernel 1 (fused prep + uv):
//   u[b][h][n] = W1[h,0:64]   . x[b,:,n]
//   v[b][h][n] = W1[h,64:128] . x[b,:,n]
//   and (for blockIdx.x==0,y==0): c[b][h] = b1[h] + W1[h,128:192].emb[b];
//   Sabs = 0.
// grid = (N_/NT, HID_/WH, B_), block = 256
// ---------------------------------------------------------------------------
__global__ __launch_bounds__(256) void uv_kernel(const float* __restrict__ x,
                                                 const float* __restrict__ emb,
                                                 const float* __restrict__ W1,
                                                 const float* __restrict__ b1) {
    __shared__ float xs[D_ * NT];  // 8 KB
    int n0  = blockIdx.x * NT;
    int h0  = blockIdx.y * WH;
    int b   = blockIdx.z;
    int tid = threadIdx.x;

    // fold "prep" into one block per b
    if (blockIdx.x == 0 && blockIdx.y == 0 && tid < HID_) {
        int h = tid;
        float acc = b1[h];
        const float4* wrow = (const float4*)(W1 + h * IN_ + 2 * D_);
        const float4* er   = (const float4*)(emb + b * E_);
#pragma unroll
        for (int e4 = 0; e4 < E_ / 4; ++e4) {
            float4 w = wrow[e4];
            float4 e = er[e4];
            acc += w.x * e.x + w.y * e.y + w.z * e.z + w.w * e.w;
        }
        g_C[b * HID_ + h] = acc;
        g_Sabs[b * HID_ + h] = 0.0f;
    }

    const float* xb = x + b * D_ * N_ + n0;
#pragma unroll
    for (int idx = tid; idx < D_ * NT; idx += 256) {
        int d = idx >> 5;
        int n = idx & (NT - 1);
        xs[idx] = xb[d * N_ + n];   // coalesced 128B rows
    }
    __syncthreads();

    int w    = tid >> 5;
    int lane = tid & 31;
    int h    = h0 + w;
    const float4* wa = (const float4*)(W1 + h * IN_);
    const float4* wb = (const float4*)(W1 + h * IN_ + D_);

    float u = 0.0f, v = 0.0f;
#pragma unroll
    for (int d4 = 0; d4 < D_ / 4; ++d4) {
        float4 a  = wa[d4];
        float4 bb = wb[d4];
        float x0 = xs[(4 * d4 + 0) * NT + lane];
        float x1 = xs[(4 * d4 + 1) * NT + lane];
        float x2 = xs[(4 * d4 + 2) * NT + lane];
        float x3 = xs[(4 * d4 + 3) * NT + lane];
        u += a.x  * x0 + a.y  * x1 + a.z  * x2 + a.w  * x3;
        v += bb.x * x0 + bb.y * x1 + bb.z * x2 + bb.w * x3;
    }
    int col = n0 + lane;
    g_U[(b * HID_ + h) * N_ + col] = u;
    g_V[(b * HID_ + h) * N_ + col] = v;
}

// ---------------------------------------------------------------------------
// Kernel 2: Sabs[b][h] += sum_{i<j} |u_i + v_j + c|
// (relu recovered later via relu(x) = (x + |x|)/2; sum(x) has a closed form)
// grid = B_*16; block = (128, 2): y=0 -> i-tile p, y=1 -> i-tile 31-p
// Inner op compiles to: FADD x=t+v ; FADD a,a,|x|   (2 instr/element)
// ---------------------------------------------------------------------------
__global__ __launch_bounds__(256) void pair_kernel() {
    int b = blockIdx.x >> 4;
    int p = blockIdx.x & 15;
    int h = threadIdx.x;                       // 0..127
    int tile = (threadIdx.y == 0) ? p : (31 - p);
    int i0 = tile * TI;

    const float* ub = g_U + (b * HID_ + h) * N_;
    const float* vb = g_V + (b * HID_ + h) * N_;
    float cb = g_C[b * HID_ + h];

    float t0[TI], a[TI];
#pragma unroll
    for (int k = 0; k < TI; ++k) {
        t0[k] = ub[i0 + k] + cb;
        a[k]  = 0.0f;
    }

    // triangular corner: j in (i0, i0+TI)
#pragma unroll
    for (int jj = 1; jj < TI; ++jj) {
        float vj = vb[i0 + jj];
#pragma unroll
        for (int k = 0; k < jj; ++k)
            a[k] += fabsf(t0[k] + vj);
    }

    // main: j in [i0+TI, N), trip count multiple of 8, 16B aligned
    for (int j = i0 + TI; j < N_; j += 8) {
        float4 v0 = *(const float4*)(vb + j);
        float4 v1 = *(const float4*)(vb + j + 4);
#pragma unroll
        for (int k = 0; k < TI; ++k) {
            a[k] += fabsf(t0[k] + v0.x);
            a[k] += fabsf(t0[k] + v0.y);
            a[k] += fabsf(t0[k] + v0.z);
            a[k] += fabsf(t0[k] + v0.w);
            a[k] += fabsf(t0[k] + v1.x);
            a[k] += fabsf(t0[k] + v1.y);
            a[k] += fabsf(t0[k] + v1.z);
            a[k] += fabsf(t0[k] + v1.w);
        }
    }

    float s = ((a[0] + a[1]) + (a[2] + a[3])) + ((a[4] + a[5]) + (a[6] + a[7]));
    atomicAdd(&g_Sabs[b * HID_ + h], s);
}

// ---------------------------------------------------------------------------
// Kernel 3 (fused linear-part + output GEMM):
//   lin[b][h] = sum_n u_n*(N-1-n) + sum_n v_n*n + c*R
//   S[b][h]   = 0.5*(lin + Sabs)
//   out[b][o] = W2[o,:].S[b,:] + R*b2[o]
// grid = B_, block = HID_
// ---------------------------------------------------------------------------
__global__ __launch_bounds__(HID_) void out_kernel(const float* __restrict__ W2,
                                                   const float* __restrict__ b2,
                                                   float* __restrict__ out) {
    __shared__ float Ss[HID_];
    int b = blockIdx.x;
    int h = threadIdx.x;

    const float4* u4 = (const float4*)(g_U + (b * HID_ + h) * N_);
    const float4* v4 = (const float4*)(g_V + (b * HID_ + h) * N_);
    float lin = 0.0f;
#pragma unroll 8
    for (int q = 0; q < N_ / 4; ++q) {
        float4 uu = u4[q];
        float4 vv = v4[q];
        float n0f = (float)(4 * q);
        lin += uu.x * (255.0f - n0f)          + vv.x * n0f;
        lin += uu.y * (255.0f - (n0f + 1.0f)) + vv.y * (n0f + 1.0f);
        lin += uu.z * (255.0f - (n0f + 2.0f)) + vv.z * (n0f + 2.0f);
        lin += uu.w * (255.0f - (n0f + 3.0f)) + vv.w * (n0f + 3.0f);
    }
    lin += g_C[b * HID_ + h] * (float)R_PAIRS;
    Ss[h] = 0.5f * (lin + g_Sabs[b * HID_ + h]);
    __syncthreads();

    if (h < OUT_) {
        int o = h;
        const float4* w = (const float4*)(W2 + o * HID_);
        const float4* s = (const float4*)Ss;
        float acc = 0.0f;
#pragma unroll
        for (int q = 0; q < HID_ / 4; ++q) {
            float4 ww = w[q];
            float4 ss = s[q];
            acc += ww.x * ss.x + ww.y * ss.y + ww.z * ss.z + ww.w * ss.w;
        }
        out[b * OUT_ + o] = acc + (float)R_PAIRS * b2[o];
    }
}

// ---------------------------------------------------------------------------
extern "C" void kernel_launch(void* const* d_in, const int* in_sizes, int n_in,
                              void* d_out, int out_size) {
    const float* x   = (const float*)d_in[0];
    const float* emb = (const float*)d_in[1];
    const float* W1  = (const float*)d_in[2];
    const float* b1  = (const float*)d_in[3];
    const float* W2  = (const float*)d_in[4];
    const float* b2  = (const float*)d_in[5];
    float* out = (float*)d_out;

    dim3 guv(N_ / NT, HID_ / WH, B_);
    uv_kernel<<<guv, 256>>>(x, emb, W1, b1);

    pair_kernel<<<B_ * 16, dim3(HID_, 2)>>>();

    out_kernel<<<B_, HID_>>>(W2, b2, out);
}

// round 3
// speedup vs baseline: 1.1960x; 1.1960x over previous
#include <cuda_runtime.h>

#define B_      16
#define D_      64
#define N_      256      // H*W
#define E_      64
#define HID_    128
#define OUT_    64
#define IN_     192      // 2*D + E
#define R_PAIRS 32640    // N*(N-1)/2
#define NB      128      // persistent blocks (must all be co-resident; <= #SMs)
#define NTH     256
#define XS_PAD  68       // 32 rows x 68 floats (padded) -> conflict-free LDS.128

// Scratch (no allocs allowed). All deterministic: every slot written every run.
__device__ float g_U[B_ * HID_ * N_];
__device__ float g_V[B_ * HID_ * N_];
__device__ float g_C[B_ * HID_];
__device__ float g_LinPart[B_ * HID_ * 8];      // per n-tile partial of linear term
__device__ float g_SabsPart[B_ * 32 * HID_];    // per i-tile partial of sum|.|
__device__ unsigned g_barCnt = 0;
__device__ volatile unsigned g_barGen = 0;

// ---------------- packed f32x2 helpers ----------------
__device__ __forceinline__ void fma2(unsigned long long& acc,
                                     unsigned long long w, unsigned long long x) {
    asm("fma.rn.f32x2 %0, %1, %2, %3;" : "=l"(acc) : "l"(w), "l"(x), "l"(acc));
}
__device__ __forceinline__ unsigned long long pack2(float a, float b) {
    unsigned long long r;
    asm("mov.b64 %0, {%1, %2};" : "=l"(r) : "f"(a), "f"(b));
    return r;
}
__device__ __forceinline__ float lo2(unsigned long long v) {
    return __uint_as_float((unsigned)(v & 0xffffffffu));
}
__device__ __forceinline__ float hi2(unsigned long long v) {
    return __uint_as_float((unsigned)(v >> 32));
}
// acc2 += |t2 + v2|  (packed): add.f32x2 (fma pipe) + and.b64 (alu) + add.f32x2
__device__ __forceinline__ void addabs2(unsigned long long& acc,
                                        unsigned long long t2, unsigned long long v2,
                                        unsigned long long mask) {
    unsigned long long x;
    asm("add.rn.f32x2 %0, %1, %2;" : "=l"(x) : "l"(t2), "l"(v2));
    asm("and.b64 %0, %1, %2;" : "=l"(x) : "l"(x), "l"(mask));
    asm("add.rn.f32x2 %0, %1, %2;" : "=l"(acc) : "l"(acc), "l"(x));
}

// ---------------- device-wide barrier (all NB blocks resident) ----------------
__device__ __forceinline__ void grid_barrier() {
    __syncthreads();
    if (threadIdx.x == 0) {
        unsigned gen = g_barGen;
        __threadfence();
        if (atomicAdd(&g_barCnt, 1u) == NB - 1) {
            g_barCnt = 0;
            __threadfence();
            g_barGen = gen + 1;
        } else {
            while (g_barGen == gen) { __nanosleep(32); }
        }
        __threadfence();
    }
    __syncthreads();
}

// ---------------------------------------------------------------------------
__global__ __launch_bounds__(NTH, 1) void fused_kernel(
    const float* __restrict__ x, const float* __restrict__ emb,
    const float* __restrict__ W1, const float* __restrict__ b1,
    const float* __restrict__ W2, const float* __restrict__ b2,
    float* __restrict__ out)
{
    __shared__ __align__(16) float xs[32 * XS_PAD];
    __shared__ float Ss[HID_];
    const int blk = blockIdx.x;
    const int tid = threadIdx.x;
    const int w    = tid >> 5;
    const int lane = tid & 31;

    // ---- c[b][h] = b1[h] + W1[h,128:192].emb[b]   (blocks 0..15) ----
    if (blk < B_ && tid < HID_) {
        int b = blk, h = tid;
        const float4* wr = (const float4*)(W1 + h * IN_ + 2 * D_);
        const float4* er = (const float4*)(emb + b * E_);
        float acc = b1[h];
#pragma unroll
        for (int e4 = 0; e4 < E_ / 4; ++e4) {
            float4 ww = wr[e4]; float4 ee = er[e4];
            acc += ww.x * ee.x + ww.y * ee.y + ww.z * ee.z + ww.w * ee.w;
        }
        g_C[b * HID_ + h] = acc;
    }

    // ================= Phase 1: U,V + lin partials =================
    // 1024 units = b(16) x hgroup(8: 16 h each) x ntile(8: 32 n each); 8 per block.
    for (int s = 0; s < 8; ++s) {
        int u  = blk * 8 + s;
        int b  = u >> 6;
        int hg = (u >> 3) & 7;
        int nt = u & 7;
        int n0 = nt * 32;

        __syncthreads();
        {   // stage x[b][0:64][n0:n0+32] transposed into xs[n][d] (pad 68)
            const float4* xg = (const float4*)(x + b * D_ * N_ + n0);
#pragma unroll
            for (int t = tid; t < 512; t += NTH) {
                int d  = t >> 3;
                int c4 = t & 7;
                float4 vv = xg[d * (N_ / 4) + c4];
                int nl = c4 * 4;
                xs[(nl + 0) * XS_PAD + d] = vv.x;
                xs[(nl + 1) * XS_PAD + d] = vv.y;
                xs[(nl + 2) * XS_PAD + d] = vv.z;
                xs[(nl + 3) * XS_PAD + d] = vv.w;
            }
        }
        __syncthreads();

        int h1 = hg * 16 + w;
        int h2 = h1 + 8;
        const ulonglong2* wa1 = (const ulonglong2*)(W1 + h1 * IN_);
        const ulonglong2* wb1 = (const ulonglong2*)(W1 + h1 * IN_ + D_);
        const ulonglong2* wa2 = (const ulonglong2*)(W1 + h2 * IN_);
        const ulonglong2* wb2 = (const ulonglong2*)(W1 + h2 * IN_ + D_);
        const ulonglong2* xr  = (const ulonglong2*)(xs + lane * XS_PAD);

        unsigned long long au1 = 0ull, av1 = 0ull, au2 = 0ull, av2 = 0ull;
#pragma unroll
        for (int d4 = 0; d4 < 16; ++d4) {
            ulonglong2 xv  = xr[d4];
            ulonglong2 A1  = wa1[d4], B1 = wb1[d4];
            ulonglong2 A2  = wa2[d4], B2 = wb2[d4];
            fma2(au1, A1.x, xv.x); fma2(au1, A1.y, xv.y);
            fma2(av1, B1.x, xv.x); fma2(av1, B1.y, xv.y);
            fma2(au2, A2.x, xv.x); fma2(au2, A2.y, xv.y);
            fma2(av2, B2.x, xv.x); fma2(av2, B2.y, xv.y);
        }
        float u1 = lo2(au1) + hi2(au1), v1 = lo2(av1) + hi2(av1);
        float u2 = lo2(au2) + hi2(au2), v2 = lo2(av2) + hi2(av2);
        int col = n0 + lane;
        g_U[(b * HID_ + h1) * N_ + col] = u1;
        g_V[(b * HID_ + h1) * N_ + col] = v1;
        g_U[(b * HID_ + h2) * N_ + col] = u2;
        g_V[(b * HID_ + h2) * N_ + col] = v2;

        // lin partial: u*(N-1-n) + v*n, warp-reduced over the 32 n of this tile
        float nf = (float)col;
        float l1 = u1 * (255.0f - nf) + v1 * nf;
        float l2 = u2 * (255.0f - nf) + v2 * nf;
#pragma unroll
        for (int o = 16; o; o >>= 1) {
            l1 += __shfl_xor_sync(0xffffffffu, l1, o);
            l2 += __shfl_xor_sync(0xffffffffu, l2, o);
        }
        if (lane == 0) {
            g_LinPart[(b * HID_ + h1) * 8 + nt] = l1;
            g_LinPart[(b * HID_ + h2) * 8 + nt] = l2;
        }
    }

    grid_barrier();

    // ================= Phase 2: Sabs partials =================
    // 256 units = (b, p in 0..15); thread: h = tid&127, y = tid>>7 picks tile p or 31-p
    {
        const unsigned long long mask = 0x7FFFFFFF7FFFFFFFull;
        int h = tid & 127;
        int y = tid >> 7;
        for (int s = 0; s < 2; ++s) {
            int u = blk * 2 + s;
            int b = u >> 4;
            int p = u & 15;
            int tile = y ? (31 - p) : p;
            int i0 = tile * 8;

            const float* ub = g_U + (b * HID_ + h) * N_;
            const float* vb = g_V + (b * HID_ + h) * N_;
            float cb = g_C[b * HID_ + h];

            float4 uu0 = *(const float4*)(ub + i0);
            float4 uu1 = *(const float4*)(ub + i0 + 4);
            float t[8] = {uu0.x + cb, uu0.y + cb, uu0.z + cb, uu0.w + cb,
                          uu1.x + cb, uu1.y + cb, uu1.z + cb, uu1.w + cb};
            unsigned long long t2[8], a2[8];
#pragma unroll
            for (int k = 0; k < 8; ++k) { t2[k] = pack2(t[k], t[k]); a2[k] = 0ull; }

            // triangular corner (within-tile pairs)
            float corner = 0.0f;
#pragma unroll
            for (int jj = 1; jj < 8; ++jj) {
                float vj = vb[i0 + jj];
#pragma unroll
                for (int k = 0; k < jj; ++k) corner += fabsf(t[k] + vj);
            }

            // main loop: j in [i0+8, 256), step 8, 32B-aligned
            for (int j = i0 + 8; j < N_; j += 8) {
                ulonglong2 va = *(const ulonglong2*)(vb + j);
                ulonglong2 vc = *(const ulonglong2*)(vb + j + 4);
#pragma unroll
                for (int k = 0; k < 8; ++k) {
                    addabs2(a2[k], t2[k], va.x, mask);
                    addabs2(a2[k], t2[k], va.y, mask);
                    addabs2(a2[k], t2[k], vc.x, mask);
                    addabs2(a2[k], t2[k], vc.y, mask);
                }
            }

            float sacc = corner;
#pragma unroll
            for (int k = 0; k < 8; ++k) sacc += lo2(a2[k]) + hi2(a2[k]);
            g_SabsPart[(b * 32 + tile) * HID_ + h] = sacc;
        }
    }

    grid_barrier();

    // ================= Phase 3: reduce + output GEMM (blocks 0..15) =================
    if (blk < B_) {
        int b = blk;
        if (tid < HID_) {
            int hh = tid;
            float lin = 0.0f;
#pragma unroll
            for (int q = 0; q < 8; ++q) lin += g_LinPart[(b * HID_ + hh) * 8 + q];
            float sab = 0.0f;
#pragma unroll
            for (int t = 0; t < 32; ++t) sab += g_SabsPart[(b * 32 + t) * HID_ + hh];
            lin += g_C[b * HID_ + hh] * (float)R_PAIRS;
            Ss[hh] = 0.5f * (lin + sab);   // sum over pairs of relu = (lin + sum|.|)/2
        }
        __syncthreads();
        if (tid < OUT_) {
            int o = tid;
            const float4* wv = (const float4*)(W2 + o * HID_);
            const float4* sv = (const float4*)Ss;
            float acc = 0.0f;
#pragma unroll
            for (int q = 0; q < HID_ / 4; ++q) {
                float4 ww = wv[q]; float4 ssv = sv[q];
                acc += ww.x * ssv.x + ww.y * ssv.y + ww.z * ssv.z + ww.w * ssv.w;
            }
            out[b * OUT_ + o] = acc + (float)R_PAIRS * b2[o];
        }
    }
}

// ---------------------------------------------------------------------------
extern "C" void kernel_launch(void* const* d_in, const int* in_sizes, int n_in,
                              void* d_out, int out_size) {
    const float* x   = (const float*)d_in[0];
    const float* emb = (const float*)d_in[1];
    const float* W1  = (const float*)d_in[2];
    const float* b1  = (const float*)d_in[3];
    const float* W2  = (const float*)d_in[4];
    const float* b2  = (const float*)d_in[5];
    float* out = (float*)d_out;

    fused_kernel<<<NB, NTH>>>(x, emb, W1, b1, W2, b2, out);
}

// round 4
// speedup vs baseline: 1.3136x; 1.0983x over previous
#include <cuda_runtime.h>

#define B_      16
#define D_      64
#define N_      256
#define E_      64
#define HID_    128
#define OUT_    64
#define IN_     192
#define R_PAIRS 32640
#define NB      128      // persistent blocks, all co-resident (<= #SMs)
#define NTH     256
#define XS_PAD  68       // x-tile transpose pad
#define US_PAD  18       // u/v transpose pad (even -> 8B-aligned LDS.64)

// Scratch. U,V layout: [b][n][h]  (h contiguous -> coalesced phase-2 loads)
__device__ float g_U[B_ * N_ * HID_];
__device__ float g_V[B_ * N_ * HID_];
__device__ float g_C[B_ * HID_];
__device__ float g_LinPart[B_ * HID_ * 8];
__device__ float g_SabsPart[B_ * 32 * HID_];
__device__ unsigned g_barCnt = 0;
__device__ volatile unsigned g_barGen = 0;

// ---------------- packed f32x2 helpers ----------------
__device__ __forceinline__ void fma2(unsigned long long& acc,
                                     unsigned long long w, unsigned long long x) {
    asm("fma.rn.f32x2 %0, %1, %2, %3;" : "=l"(acc) : "l"(w), "l"(x), "l"(acc));
}
__device__ __forceinline__ unsigned long long pack2(float a, float b) {
    unsigned long long r;
    asm("mov.b64 %0, {%1, %2};" : "=l"(r) : "f"(a), "f"(b));
    return r;
}
__device__ __forceinline__ float lo2(unsigned long long v) {
    return __uint_as_float((unsigned)(v & 0xffffffffu));
}
__device__ __forceinline__ float hi2(unsigned long long v) {
    return __uint_as_float((unsigned)(v >> 32));
}
__device__ __forceinline__ void add2(unsigned long long& acc, unsigned long long x) {
    asm("add.rn.f32x2 %0, %1, %2;" : "=l"(acc) : "l"(acc), "l"(x));
}
// acc2 += |t2 + v2| (packed over an h-pair)
__device__ __forceinline__ void addabs2(unsigned long long& acc,
                                        unsigned long long t2, unsigned long long v2,
                                        unsigned long long mask) {
    unsigned long long x;
    asm("add.rn.f32x2 %0, %1, %2;" : "=l"(x) : "l"(t2), "l"(v2));
    asm("and.b64 %0, %1, %2;" : "=l"(x) : "l"(x), "l"(mask));
    asm("add.rn.f32x2 %0, %1, %2;" : "=l"(acc) : "l"(acc), "l"(x));
}

// ---------------- device-wide barrier ----------------
__device__ __forceinline__ void grid_barrier() {
    __syncthreads();
    if (threadIdx.x == 0) {
        unsigned gen = g_barGen;
        __threadfence();
        if (atomicAdd(&g_barCnt, 1u) == NB - 1) {
            g_barCnt = 0;
            __threadfence();
            g_barGen = gen + 1;
        } else {
            while (g_barGen == gen) { __nanosleep(16); }
        }
        __threadfence();
    }
    __syncthreads();
}

// ---------------------------------------------------------------------------
__global__ __launch_bounds__(NTH, 1) void fused_kernel(
    const float* __restrict__ x, const float* __restrict__ emb,
    const float* __restrict__ W1, const float* __restrict__ b1,
    const float* __restrict__ W2, const float* __restrict__ b2,
    float* __restrict__ out)
{
    __shared__ __align__(16) float xs[32 * XS_PAD];
    __shared__ __align__(16) float us[32 * US_PAD];
    __shared__ __align__(16) float vs[32 * US_PAD];
    __shared__ float Ss[HID_];
    const int blk  = blockIdx.x;
    const int tid  = threadIdx.x;
    const int w    = tid >> 5;
    const int lane = tid & 31;

    // ---- c[b][h] = b1[h] + W1[h,128:192].emb[b]  (blocks 0..15) ----
    if (blk < B_ && tid < HID_) {
        int b = blk, h = tid;
        const float4* wr = (const float4*)(W1 + h * IN_ + 2 * D_);
        const float4* er = (const float4*)(emb + b * E_);
        float acc = b1[h];
#pragma unroll
        for (int e4 = 0; e4 < E_ / 4; ++e4) {
            float4 ww = wr[e4]; float4 ee = er[e4];
            acc += ww.x * ee.x + ww.y * ee.y + ww.z * ee.z + ww.w * ee.w;
        }
        g_C[b * HID_ + h] = acc;
    }

    // ================= Phase 1: U,V (transposed store) + lin partials ========
    // 1024 units = b(16) x hgroup(8: 16 h) x ntile(8: 32 n); 8 per block.
    for (int s = 0; s < 8; ++s) {
        int u  = blk * 8 + s;
        int b  = u >> 6;
        int hg = (u >> 3) & 7;
        int nt = u & 7;
        int n0 = nt * 32;

        __syncthreads();   // protect xs reuse
        {
            const float4* xg = (const float4*)(x + b * D_ * N_ + n0);
#pragma unroll
            for (int t = tid; t < 512; t += NTH) {
                int d  = t >> 3;
                int c4 = t & 7;
                float4 vv = xg[d * (N_ / 4) + c4];
                int nl = c4 * 4;
                xs[(nl + 0) * XS_PAD + d] = vv.x;
                xs[(nl + 1) * XS_PAD + d] = vv.y;
                xs[(nl + 2) * XS_PAD + d] = vv.z;
                xs[(nl + 3) * XS_PAD + d] = vv.w;
            }
        }
        __syncthreads();

        int h1 = hg * 16 + w;     // local h = w
        int h2 = h1 + 8;          // local h = w + 8
        const ulonglong2* wa1 = (const ulonglong2*)(W1 + h1 * IN_);
        const ulonglong2* wb1 = (const ulonglong2*)(W1 + h1 * IN_ + D_);
        const ulonglong2* wa2 = (const ulonglong2*)(W1 + h2 * IN_);
        const ulonglong2* wb2 = (const ulonglong2*)(W1 + h2 * IN_ + D_);
        const ulonglong2* xr  = (const ulonglong2*)(xs + lane * XS_PAD);

        unsigned long long au1 = 0ull, av1 = 0ull, au2 = 0ull, av2 = 0ull;
#pragma unroll 8
        for (int d4 = 0; d4 < 16; ++d4) {
            ulonglong2 xv = xr[d4];
            ulonglong2 A1 = wa1[d4], B1 = wb1[d4];
            ulonglong2 A2 = wa2[d4], B2 = wb2[d4];
            fma2(au1, A1.x, xv.x); fma2(au1, A1.y, xv.y);
            fma2(av1, B1.x, xv.x); fma2(av1, B1.y, xv.y);
            fma2(au2, A2.x, xv.x); fma2(au2, A2.y, xv.y);
            fma2(av2, B2.x, xv.x); fma2(av2, B2.y, xv.y);
        }
        float u1 = lo2(au1) + hi2(au1), v1 = lo2(av1) + hi2(av1);
        float u2 = lo2(au2) + hi2(au2), v2 = lo2(av2) + hi2(av2);

        // lin partials (closed-form of sum over pairs of the linear term)
        float nf = (float)(n0 + lane);
        float l1 = u1 * (255.0f - nf) + v1 * nf;
        float l2 = u2 * (255.0f - nf) + v2 * nf;
#pragma unroll
        for (int o = 16; o; o >>= 1) {
            l1 += __shfl_xor_sync(0xffffffffu, l1, o);
            l2 += __shfl_xor_sync(0xffffffffu, l2, o);
        }
        if (lane == 0) {
            g_LinPart[(b * HID_ + h1) * 8 + nt] = l1;
            g_LinPart[(b * HID_ + h2) * 8 + nt] = l2;
        }

        // transpose via smem: us[n][hh] (pad 18)
        us[lane * US_PAD + w]     = u1;
        us[lane * US_PAD + w + 8] = u2;
        vs[lane * US_PAD + w]     = v1;
        vs[lane * US_PAD + w + 8] = v2;
        __syncthreads();

        // coalesced store: thread -> (n = tid>>3, hp = tid&7), STG.64
        {
            int n  = tid >> 3;
            int hp = tid & 7;
            float2 uu = *(const float2*)(us + n * US_PAD + 2 * hp);
            float2 vv = *(const float2*)(vs + n * US_PAD + 2 * hp);
            int row = b * N_ + n0 + n;
            ((float2*)g_U)[row * (HID_ / 2) + hg * 8 + hp] = uu;
            ((float2*)g_V)[row * (HID_ / 2) + hg * 8 + hp] = vv;
        }
    }

    grid_barrier();

    // ================= Phase 2: Sabs partials (h-pair packed, coalesced) =====
    // block = (b, pg in 0..7): tiles {2pg, 2pg+1, 31-2pg, 30-2pg}.
    // warp->tile map gives each SMSP one heavy + one light tile (248 j total).
    {
        const unsigned long long mask = 0x7FFFFFFF7FFFFFFFull;
        int b  = blk >> 3;
        int pg = blk & 7;
        int ti = (w < 4) ? w : ((w + 2) & 3);
        int hp = ((w < 4) ? 0 : 32) + lane;            // h-pair index 0..63
        int tile = (ti == 0) ? 2 * pg
                 : (ti == 1) ? 2 * pg + 1
                 : (ti == 2) ? 31 - 2 * pg
                 :             30 - 2 * pg;
        int i0 = tile * 8;

        const float2* U2 = (const float2*)g_U + (size_t)b * N_ * (HID_ / 2) + hp;
        const float2* V2 = (const float2*)g_V + (size_t)b * N_ * (HID_ / 2) + hp;
        float2 cc = ((const float2*)g_C)[b * (HID_ / 2) + hp];

        unsigned long long t2[8], a2[8];
#pragma unroll
        for (int k = 0; k < 8; ++k) {
            float2 uu = U2[(i0 + k) * (HID_ / 2)];
            t2[k] = pack2(uu.x + cc.x, uu.y + cc.y);
            a2[k] = 0ull;
        }

        // triangular corner
#pragma unroll
        for (int jj = 1; jj < 8; ++jj) {
            float2 vv = V2[(i0 + jj) * (HID_ / 2)];
            unsigned long long v2 = pack2(vv.x, vv.y);
#pragma unroll
            for (int k = 0; k < jj; ++k) addabs2(a2[k], t2[k], v2, mask);
        }

        // main: j in [i0+8, 256), 4 j per iteration (coalesced LDG.64)
        for (int j = i0 + 8; j < N_; j += 4) {
            float2 va = V2[(j + 0) * (HID_ / 2)];
            float2 vb = V2[(j + 1) * (HID_ / 2)];
            float2 vc = V2[(j + 2) * (HID_ / 2)];
            float2 vd = V2[(j + 3) * (HID_ / 2)];
            unsigned long long p0 = pack2(va.x, va.y);
            unsigned long long p1 = pack2(vb.x, vb.y);
            unsigned long long p2 = pack2(vc.x, vc.y);
            unsigned long long p3 = pack2(vd.x, vd.y);
#pragma unroll
            for (int k = 0; k < 8; ++k) {
                addabs2(a2[k], t2[k], p0, mask);
                addabs2(a2[k], t2[k], p1, mask);
                addabs2(a2[k], t2[k], p2, mask);
                addabs2(a2[k], t2[k], p3, mask);
            }
        }

        unsigned long long s2 = a2[0];
        add2(s2, a2[1]); add2(s2, a2[2]); add2(s2, a2[3]);
        add2(s2, a2[4]); add2(s2, a2[5]); add2(s2, a2[6]); add2(s2, a2[7]);
        float2 res = {lo2(s2), hi2(s2)};
        ((float2*)g_SabsPart)[(b * 32 + tile) * (HID_ / 2) + hp] = res;
    }

    grid_barrier();

    // ================= Phase 3: reduce + output GEMM (blocks 0..15) ==========
    if (blk < B_) {
        int b = blk;
        if (tid < HID_) {
            int hh = tid;
            float lin = 0.0f;
#pragma unroll
            for (int q = 0; q < 8; ++q) lin += g_LinPart[(b * HID_ + hh) * 8 + q];
            float sab = 0.0f;
#pragma unroll
            for (int t = 0; t < 32; ++t) sab += g_SabsPart[(b * 32 + t) * HID_ + hh];
            lin += g_C[b * HID_ + hh] * (float)R_PAIRS;
            Ss[hh] = 0.5f * (lin + sab);
        }
        __syncthreads();
        if (tid < OUT_) {
            int o = tid;
            const float4* wv = (const float4*)(W2 + o * HID_);
            const float4* sv = (const float4*)Ss;
            float acc = 0.0f;
#pragma unroll
            for (int q = 0; q < HID_ / 4; ++q) {
                float4 ww = wv[q]; float4 ssv = sv[q];
                acc += ww.x * ssv.x + ww.y * ssv.y + ww.z * ssv.z + ww.w * ssv.w;
            }
            out[b * OUT_ + o] = acc + (float)R_PAIRS * b2[o];
        }
    }
}

// ---------------------------------------------------------------------------
extern "C" void kernel_launch(void* const* d_in, const int* in_sizes, int n_in,
                              void* d_out, int out_size) {
    const float* x   = (const float*)d_in[0];
    const float* emb = (const float*)d_in[1];
    const float* W1  = (const float*)d_in[2];
    const float* b1  = (const float*)d_in[3];
    const float* W2  = (const float*)d_in[4];
    const float* b2  = (const float*)d_in[5];
    float* out = (float*)d_out;

    fused_kernel<<<NB, NTH>>>(x, emb, W1, b1, W2, b2, out);
}

// round 5
// speedup vs baseline: 1.5212x; 1.1581x over previous
#include <cuda_runtime.h>

#define B_      16
#define D_      64
#define N_      256
#define E_      64
#define HID_    128
#define OUT_    64
#define IN_     192
#define R_PAIRS 32640
#define NB      256      // persistent blocks; 2/SM on 148 SMs -> all co-resident
#define NTH     256
#define XS_PAD  68
#define US_PAD  18

// Scratch. U,V layout: [b][n][h]
__device__ float g_U[B_ * N_ * HID_];
__device__ float g_V[B_ * N_ * HID_];
__device__ float g_C[B_ * HID_];
__device__ float g_LinPart[B_ * HID_ * 8];
__device__ float g_SabsPart[B_ * 32 * 2 * HID_];   // [b][tile][jhalf][h]
__device__ unsigned g_barCnt = 0;
__device__ volatile unsigned g_barGen = 0;

// ---------------- packed f32x2 helpers ----------------
__device__ __forceinline__ void fma2(unsigned long long& acc,
                                     unsigned long long w, unsigned long long x) {
    asm("fma.rn.f32x2 %0, %1, %2, %3;" : "=l"(acc) : "l"(w), "l"(x), "l"(acc));
}
__device__ __forceinline__ unsigned long long pack2(float a, float b) {
    unsigned long long r;
    asm("mov.b64 %0, {%1, %2};" : "=l"(r) : "f"(a), "f"(b));
    return r;
}
__device__ __forceinline__ float lo2(unsigned long long v) {
    return __uint_as_float((unsigned)(v & 0xffffffffu));
}
__device__ __forceinline__ float hi2(unsigned long long v) {
    return __uint_as_float((unsigned)(v >> 32));
}
__device__ __forceinline__ void add2(unsigned long long& acc, unsigned long long x) {
    asm("add.rn.f32x2 %0, %1, %2;" : "=l"(acc) : "l"(acc), "l"(x));
}
__device__ __forceinline__ void addabs2(unsigned long long& acc,
                                        unsigned long long t2, unsigned long long v2,
                                        unsigned long long mask) {
    unsigned long long x;
    asm("add.rn.f32x2 %0, %1, %2;" : "=l"(x) : "l"(t2), "l"(v2));
    asm("and.b64 %0, %1, %2;" : "=l"(x) : "l"(x), "l"(mask));
    asm("add.rn.f32x2 %0, %1, %2;" : "=l"(acc) : "l"(acc), "l"(x));
}

// ---------------- device-wide barrier (all NB blocks resident) ----------------
__device__ __forceinline__ void grid_barrier() {
    __syncthreads();
    if (threadIdx.x == 0) {
        unsigned gen = g_barGen;
        __threadfence();
        if (atomicAdd(&g_barCnt, 1u) == NB - 1) {
            g_barCnt = 0;
            __threadfence();
            g_barGen = gen + 1;
        } else {
            while (g_barGen == gen) { __nanosleep(16); }
        }
        __threadfence();
    }
    __syncthreads();
}

// ---------------------------------------------------------------------------
__global__ __launch_bounds__(NTH, 2) void fused_kernel(
    const float* __restrict__ x, const float* __restrict__ emb,
    const float* __restrict__ W1, const float* __restrict__ b1,
    const float* __restrict__ W2, const float* __restrict__ b2,
    float* __restrict__ out)
{
    __shared__ __align__(16) float xs[32 * XS_PAD];
    __shared__ __align__(16) float us[32 * US_PAD];
    __shared__ __align__(16) float vs[32 * US_PAD];
    __shared__ float Ss[HID_];
    const int blk  = blockIdx.x;
    const int tid  = threadIdx.x;
    const int w    = tid >> 5;
    const int lane = tid & 31;

    // ---- c[b][h] = b1[h] + W1[h,128:192].emb[b]  (blocks 0..15) ----
    if (blk < B_ && tid < HID_) {
        int b = blk, h = tid;
        const float4* wr = (const float4*)(W1 + h * IN_ + 2 * D_);
        const float4* er = (const float4*)(emb + b * E_);
        float acc = b1[h];
#pragma unroll
        for (int e4 = 0; e4 < E_ / 4; ++e4) {
            float4 ww = wr[e4]; float4 ee = er[e4];
            acc += ww.x * ee.x + ww.y * ee.y + ww.z * ee.z + ww.w * ee.w;
        }
        g_C[b * HID_ + h] = acc;
    }

    // ================= Phase 1: U,V (transposed store) + lin partials ========
    // 1024 units = b(16) x hgroup(8) x ntile(8); 4 per block.
#pragma unroll 1
    for (int s = 0; s < 4; ++s) {
        int u  = blk * 4 + s;
        int b  = u >> 6;
        int hg = (u >> 3) & 7;
        int nt = u & 7;
        int n0 = nt * 32;

        __syncthreads();
        {
            const float4* xg = (const float4*)(x + b * D_ * N_ + n0);
#pragma unroll
            for (int t = tid; t < 512; t += NTH) {
                int d  = t >> 3;
                int c4 = t & 7;
                float4 vv = xg[d * (N_ / 4) + c4];
                int nl = c4 * 4;
                xs[(nl + 0) * XS_PAD + d] = vv.x;
                xs[(nl + 1) * XS_PAD + d] = vv.y;
                xs[(nl + 2) * XS_PAD + d] = vv.z;
                xs[(nl + 3) * XS_PAD + d] = vv.w;
            }
        }
        __syncthreads();

        int h1 = hg * 16 + w;
        int h2 = h1 + 8;
        const ulonglong2* wa1 = (const ulonglong2*)(W1 + h1 * IN_);
        const ulonglong2* wb1 = (const ulonglong2*)(W1 + h1 * IN_ + D_);
        const ulonglong2* wa2 = (const ulonglong2*)(W1 + h2 * IN_);
        const ulonglong2* wb2 = (const ulonglong2*)(W1 + h2 * IN_ + D_);
        const ulonglong2* xr  = (const ulonglong2*)(xs + lane * XS_PAD);

        unsigned long long au1 = 0ull, av1 = 0ull, au2 = 0ull, av2 = 0ull;
#pragma unroll 8
        for (int d4 = 0; d4 < 16; ++d4) {
            ulonglong2 xv = xr[d4];
            ulonglong2 A1 = wa1[d4], B1 = wb1[d4];
            ulonglong2 A2 = wa2[d4], B2 = wb2[d4];
            fma2(au1, A1.x, xv.x); fma2(au1, A1.y, xv.y);
            fma2(av1, B1.x, xv.x); fma2(av1, B1.y, xv.y);
            fma2(au2, A2.x, xv.x); fma2(au2, A2.y, xv.y);
            fma2(av2, B2.x, xv.x); fma2(av2, B2.y, xv.y);
        }
        float u1 = lo2(au1) + hi2(au1), v1 = lo2(av1) + hi2(av1);
        float u2 = lo2(au2) + hi2(au2), v2 = lo2(av2) + hi2(av2);

        float nf = (float)(n0 + lane);
        float l1 = u1 * (255.0f - nf) + v1 * nf;
        float l2 = u2 * (255.0f - nf) + v2 * nf;
#pragma unroll
        for (int o = 16; o; o >>= 1) {
            l1 += __shfl_xor_sync(0xffffffffu, l1, o);
            l2 += __shfl_xor_sync(0xffffffffu, l2, o);
        }
        if (lane == 0) {
            g_LinPart[(b * HID_ + h1) * 8 + nt] = l1;
            g_LinPart[(b * HID_ + h2) * 8 + nt] = l2;
        }

        us[lane * US_PAD + w]     = u1;
        us[lane * US_PAD + w + 8] = u2;
        vs[lane * US_PAD + w]     = v1;
        vs[lane * US_PAD + w + 8] = v2;
        __syncthreads();

        {
            int n  = tid >> 3;
            int hp = tid & 7;
            float2 uu = *(const float2*)(us + n * US_PAD + 2 * hp);
            float2 vv = *(const float2*)(vs + n * US_PAD + 2 * hp);
            int row = b * N_ + n0 + n;
            ((float2*)g_U)[row * (HID_ / 2) + hg * 8 + hp] = uu;
            ((float2*)g_V)[row * (HID_ / 2) + hg * 8 + hp] = vv;
        }
    }

    grid_barrier();

    // ================= Phase 2: Sabs partials ================================
    // 256 units = (b, pg in 0..7, jhalf). Block: 4 tiles {2pg,2pg+1,31-2pg,30-2pg},
    // warp -> (tile, hp-half); each warp covers its half of the j-range.
    // Per SMSP: heavy-tile half + light-tile half = 124 j columns (balanced).
    {
        const unsigned long long mask = 0x7FFFFFFF7FFFFFFFull;
        int b  = blk >> 4;
        int pg = (blk >> 1) & 7;
        int jh = blk & 1;
        int ti = (w < 4) ? w : ((w + 2) & 3);
        int hp = ((w < 4) ? 0 : 32) + lane;
        int tile = (ti == 0) ? 2 * pg
                 : (ti == 1) ? 2 * pg + 1
                 : (ti == 2) ? 31 - 2 * pg
                 :             30 - 2 * pg;
        int i0  = tile * 8;
        int mid = 4 * tile + 132;               // midpoint of [i0+8, 256), mult of 4
        int jlo = jh ? mid : (i0 + 8);
        int jhi = jh ? N_  : mid;

        const float2* U2 = (const float2*)g_U + (size_t)b * N_ * (HID_ / 2) + hp;
        const float2* V2 = (const float2*)g_V + (size_t)b * N_ * (HID_ / 2) + hp;
        float2 cc = ((const float2*)g_C)[b * (HID_ / 2) + hp];

        unsigned long long t2[8], a2[8];
#pragma unroll
        for (int k = 0; k < 8; ++k) {
            float2 uu = U2[(i0 + k) * (HID_ / 2)];
            t2[k] = pack2(uu.x + cc.x, uu.y + cc.y);
            a2[k] = 0ull;
        }

        // triangular corner: only the jhalf==0 block
        if (jh == 0) {
#pragma unroll
            for (int jj = 1; jj < 8; ++jj) {
                float2 vv = V2[(i0 + jj) * (HID_ / 2)];
                unsigned long long v2 = pack2(vv.x, vv.y);
#pragma unroll
                for (int k = 0; k < jj; ++k) addabs2(a2[k], t2[k], v2, mask);
            }
        }

        for (int j = jlo; j < jhi; j += 4) {
            float2 va = V2[(j + 0) * (HID_ / 2)];
            float2 vb = V2[(j + 1) * (HID_ / 2)];
            float2 vc = V2[(j + 2) * (HID_ / 2)];
            float2 vd = V2[(j + 3) * (HID_ / 2)];
            unsigned long long p0 = pack2(va.x, va.y);
            unsigned long long p1 = pack2(vb.x, vb.y);
            unsigned long long p2 = pack2(vc.x, vc.y);
            unsigned long long p3 = pack2(vd.x, vd.y);
#pragma unroll
            for (int k = 0; k < 8; ++k) {
                addabs2(a2[k], t2[k], p0, mask);
                addabs2(a2[k], t2[k], p1, mask);
                addabs2(a2[k], t2[k], p2, mask);
                addabs2(a2[k], t2[k], p3, mask);
            }
        }

        unsigned long long s2 = a2[0];
        add2(s2, a2[1]); add2(s2, a2[2]); add2(s2, a2[3]);
        add2(s2, a2[4]); add2(s2, a2[5]); add2(s2, a2[6]); add2(s2, a2[7]);
        float2 res = {lo2(s2), hi2(s2)};
        ((float2*)g_SabsPart)[((b * 32 + tile) * 2 + jh) * (HID_ / 2) + hp] = res;
    }

    grid_barrier();

    // ================= Phase 3: reduce + output GEMM (blocks 0..15) ==========
    if (blk < B_) {
        int b = blk;
        if (tid < HID_) {
            int hh = tid;
            float lin = 0.0f;
#pragma unroll
            for (int q = 0; q < 8; ++q) lin += g_LinPart[(b * HID_ + hh) * 8 + q];
            float sab = 0.0f;
#pragma unroll
            for (int t = 0; t < 64; ++t)
                sab += g_SabsPart[(b * 64 + t) * HID_ + hh];
            lin += g_C[b * HID_ + hh] * (float)R_PAIRS;
            Ss[hh] = 0.5f * (lin + sab);
        }
        __syncthreads();
        if (tid < OUT_) {
            int o = tid;
            const float4* wv = (const float4*)(W2 + o * HID_);
            const float4* sv = (const float4*)Ss;
            float acc = 0.0f;
#pragma unroll
            for (int q = 0; q < HID_ / 4; ++q) {
                float4 ww = wv[q]; float4 ssv = sv[q];
                acc += ww.x * ssv.x + ww.y * ssv.y + ww.z * ssv.z + ww.w * ssv.w;
            }
            out[b * OUT_ + o] = acc + (float)R_PAIRS * b2[o];
        }
    }
}

// ---------------------------------------------------------------------------
extern "C" void kernel_launch(void* const* d_in, const int* in_sizes, int n_in,
                              void* d_out, int out_size) {
    const float* x   = (const float*)d_in[0];
    const float* emb = (const float*)d_in[1];
    const float* W1  = (const float*)d_in[2];
    const float* b1  = (const float*)d_in[3];
    const float* W2  = (const float*)d_in[4];
    const float* b2  = (const float*)d_in[5];
    float* out = (float*)d_out;

    fused_kernel<<<NB, NTH>>>(x, emb, W1, b1, W2, b2, out);
}